// round 1
// baseline (speedup 1.0000x reference)
#include <cuda_runtime.h>
#include <math.h>

#define KC 8
#define GRID 304
#define NTHREADS 256

struct Pre {
    float A[KC][10];   // scaled lower-triangular rows of M^{-1}
    float B[KC][4];    // -scaled * A * mu
    float C2[KC];      // log2 of density coefficient
    float WP[36];      // packed symmetric W (diag once, off-diag doubled)
    double logz;
};
__device__ Pre g_pre;
__device__ double g_part[GRID];

// ---------------- setup: all O(K^2) precomputation, 64 threads ----------------
__global__ void gmm_setup(const float* __restrict__ means,
                          const float* __restrict__ chols,
                          const float* __restrict__ weights) {
    __shared__ double sig[KC][4][4];
    __shared__ double Wsh[KC][KC];
    __shared__ double zpart[64];
    __shared__ double sc0, sc1;
    const int t = threadIdx.x;
    const double LOG2E = 1.4426950408889634074;
    const double LN2PI = 1.8378770664093454836;

    if (t < KC) {
        const int k = t;
        double L[4][4], S[4][4];
        for (int i2 = 0; i2 < 4; i2++)
            for (int j2 = 0; j2 < 4; j2++)
                L[i2][j2] = (j2 <= i2) ? (double)chols[k * 16 + i2 * 4 + j2] : 0.0;
        // sigma = L L^T + I
        for (int i2 = 0; i2 < 4; i2++)
            for (int j2 = 0; j2 < 4; j2++) {
                double s = (i2 == j2) ? 1.0 : 0.0;
                for (int m = 0; m < 4; m++) s += L[i2][m] * L[j2][m];
                S[i2][j2] = s;
                sig[k][i2][j2] = s;
            }
        // Cholesky: S = M M^T (lower)
        double M[4][4] = {};
        for (int i2 = 0; i2 < 4; i2++)
            for (int j2 = 0; j2 <= i2; j2++) {
                double s = S[i2][j2];
                for (int m = 0; m < j2; m++) s -= M[i2][m] * M[j2][m];
                if (i2 == j2) M[i2][i2] = sqrt(s);
                else          M[i2][j2] = s / M[j2][j2];
            }
        // A = M^{-1} (lower triangular)
        double A[4][4] = {};
        for (int i2 = 0; i2 < 4; i2++) {
            A[i2][i2] = 1.0 / M[i2][i2];
            for (int j2 = 0; j2 < i2; j2++) {
                double s = 0;
                for (int m = j2; m < i2; m++) s += M[i2][m] * A[m][j2];
                A[i2][j2] = -s * A[i2][i2];
            }
        }
        double logdet = 2.0 * (log(M[0][0]) + log(M[1][1]) + log(M[2][2]) + log(M[3][3]));
        // dens = exp2(c2 - ||A' x + b'||^2), A' = A*sqrt(0.5*log2e)
        double c2  = -0.5 * (4.0 * LN2PI + logdet) * LOG2E;
        double scl = sqrt(0.5 * LOG2E);
        int idx = 0;
        for (int i2 = 0; i2 < 4; i2++)
            for (int j2 = 0; j2 <= i2; j2++)
                g_pre.A[k][idx++] = (float)(A[i2][j2] * scl);
        for (int i2 = 0; i2 < 4; i2++) {
            double b = 0;
            for (int j2 = 0; j2 <= i2; j2++) b += A[i2][j2] * (double)means[k * 4 + j2];
            g_pre.B[k][i2] = (float)(-b * scl);
        }
        g_pre.C2[k] = (float)c2;
    }
    __syncthreads();

    // ---- W = softmax(w_i * w_j) over all 64 entries ----
    const int i = t >> 3, j = t & 7;
    double wij = (double)weights[i] * (double)weights[j];
    Wsh[i][j] = wij;
    __syncthreads();
    if (t == 0) {
        double m = Wsh[0][0];
        for (int a = 0; a < KC; a++)
            for (int b = 0; b < KC; b++)
                if (Wsh[a][b] > m) m = Wsh[a][b];
        sc0 = m;
    }
    __syncthreads();
    double e = exp(wij - sc0);
    Wsh[i][j] = e;
    __syncthreads();
    if (t == 0) {
        double s = 0;
        for (int a = 0; a < KC; a++)
            for (int b = 0; b < KC; b++) s += Wsh[a][b];
        sc1 = 1.0 / s;
    }
    __syncthreads();
    double Wij = e * sc1;
    Wsh[i][j] = Wij;
    __syncthreads();
    if (t == 0) {
        int idx = 0;
        for (int a = 0; a < KC; a++) {
            g_pre.WP[idx++] = (float)Wsh[a][a];
            for (int b = a + 1; b < KC; b++) g_pre.WP[idx++] = (float)(2.0 * Wsh[a][b]);
        }
    }

    // ---- z = sum_ij W_ij * N(mu_i; mu_j, S_i + S_j), one pair per thread ----
    {
        double Ss[4][4];
        for (int r = 0; r < 4; r++)
            for (int c = 0; c < 4; c++) Ss[r][c] = sig[i][r][c] + sig[j][r][c];
        double M[4][4] = {};
        for (int r = 0; r < 4; r++)
            for (int c = 0; c <= r; c++) {
                double s = Ss[r][c];
                for (int m = 0; m < c; m++) s -= M[r][m] * M[c][m];
                if (r == c) M[r][r] = sqrt(s);
                else        M[r][c] = s / M[c][c];
            }
        double ld = 2.0 * (log(M[0][0]) + log(M[1][1]) + log(M[2][2]) + log(M[3][3]));
        double y[4];
        for (int r = 0; r < 4; r++) {
            double s = (double)means[i * 4 + r] - (double)means[j * 4 + r];
            for (int m = 0; m < r; m++) s -= M[r][m] * y[m];
            y[r] = s / M[r][r];
        }
        double md = y[0] * y[0] + y[1] * y[1] + y[2] * y[2] + y[3] * y[3];
        double nt = exp(-0.5 * md - 0.5 * (4.0 * LN2PI + ld));
        zpart[t] = Wij * nt;
    }
    __syncthreads();
    if (t == 0) {
        double z = 0;
        for (int a = 0; a < 64; a++) z += zpart[a];
        g_pre.logz = log(z);
    }
}

// ---------------- main: per-point densities + W-quadratic + reduction ----------------
__global__ void __launch_bounds__(NTHREADS) gmm_main(const float4* __restrict__ X, int N) {
    // pull all constants into registers once
    float A[KC][10], B[KC][4], C2[KC], WP[36];
#pragma unroll
    for (int k = 0; k < KC; k++) {
#pragma unroll
        for (int t = 0; t < 10; t++) A[k][t] = g_pre.A[k][t];
#pragma unroll
        for (int t = 0; t < 4; t++)  B[k][t] = g_pre.B[k][t];
        C2[k] = g_pre.C2[k];
    }
#pragma unroll
    for (int t = 0; t < 36; t++) WP[t] = g_pre.WP[t];

    double acc = 0.0;
    const int stride = gridDim.x * blockDim.x;
    for (int i = blockIdx.x * blockDim.x + threadIdx.x; i < N; i += stride) {
        float4 x = X[i];
        float d[KC];
#pragma unroll
        for (int k = 0; k < KC; k++) {
            float y0 = fmaf(A[k][0], x.x, B[k][0]);
            float y1 = fmaf(A[k][1], x.x, fmaf(A[k][2], x.y, B[k][1]));
            float y2 = fmaf(A[k][3], x.x, fmaf(A[k][4], x.y, fmaf(A[k][5], x.z, B[k][2])));
            float y3 = fmaf(A[k][6], x.x, fmaf(A[k][7], x.y, fmaf(A[k][8], x.z, fmaf(A[k][9], x.w, B[k][3]))));
            float tq = C2[k];
            tq = fmaf(-y0, y0, tq);
            tq = fmaf(-y1, y1, tq);
            tq = fmaf(-y2, y2, tq);
            tq = fmaf(-y3, y3, tq);
            float ev;
            asm("ex2.approx.f32 %0, %1;" : "=f"(ev) : "f"(tq));
            d[k] = ev;
        }
        // num = d^T W d, symmetric packing (36 + 8 FMA)
        float num = 0.f;
        int idx = 0;
#pragma unroll
        for (int a = 0; a < KC; a++) {
            float h = WP[idx++] * d[a];
#pragma unroll
            for (int b = a + 1; b < KC; b++) h = fmaf(WP[idx++], d[b], h);
            num = fmaf(d[a], h, num);
        }
        acc += (double)num;
    }

    // block reduction (double)
    unsigned full = 0xffffffffu;
#pragma unroll
    for (int o = 16; o > 0; o >>= 1) acc += __shfl_down_sync(full, acc, o);
    __shared__ double sred[NTHREADS / 32];
    int w = threadIdx.x >> 5, l = threadIdx.x & 31;
    if (l == 0) sred[w] = acc;
    __syncthreads();
    if (w == 0) {
        double v = (l < NTHREADS / 32) ? sred[l] : 0.0;
#pragma unroll
        for (int o = 4; o > 0; o >>= 1) v += __shfl_down_sync(full, v, o);
        if (l == 0) g_part[blockIdx.x] = v;
    }
}

// ---------------- finalize ----------------
__global__ void gmm_final(float* __restrict__ out, int N) {
    double s = 0;
    for (int b = 0; b < GRID; b++) s += g_part[b];
    out[0] = (float)(-(log(s) - g_pre.logz) / (double)N);
}

extern "C" void kernel_launch(void* const* d_in, const int* in_sizes, int n_in,
                              void* d_out, int out_size) {
    const float* X       = (const float*)d_in[0];
    const float* means   = (const float*)d_in[1];
    const float* chols   = (const float*)d_in[2];
    const float* weights = (const float*)d_in[3];
    const int N = in_sizes[0] / 4;
    float* out = (float*)d_out;

    gmm_setup<<<1, 64>>>(means, chols, weights);
    gmm_main<<<GRID, NTHREADS>>>((const float4*)X, N);
    gmm_final<<<1, 1>>>(out, N);
}

// round 2
// speedup vs baseline: 2.1185x; 2.1185x over previous
#include <cuda_runtime.h>
#include <math.h>

#define KC 8
#define GRID 296
#define NTHREADS 256

struct Pre {
    float A[KC][10];   // scaled lower-triangular rows of M^{-1}
    float B[KC][4];    // -scaled * A * mu
    float C2[KC];      // log2 of density coefficient
    float WP[36];      // packed symmetric W (diag once, off-diag doubled)
    float logz;
};
__device__ Pre g_pre;
__device__ double g_part[GRID];

// ---------------- setup: all O(K^2) precomputation, fp32, fully unrolled ----------------
__global__ void gmm_setup(const float* __restrict__ means,
                          const float* __restrict__ chols,
                          const float* __restrict__ weights) {
    __shared__ float sig[KC][16];
    __shared__ float Wsh[KC][KC];
    __shared__ float zpart[64];
    __shared__ float red0[2], red1[2], red2[2];
    const int t = threadIdx.x;
    const int lane = t & 31, warp = t >> 5;
    const unsigned full = 0xffffffffu;
    const float LOG2E  = 1.4426950408889634f;
    const float LN2PI  = 1.8378770664093454f;
    const float SCL    = 0.8493218002880191f;  // sqrt(0.5*log2(e))

    // ---- per-cluster: sigma, Cholesky, inverse, density constants ----
    if (t < KC) {
        const int k = t;
        float L[4][4];
#pragma unroll
        for (int r = 0; r < 4; r++)
#pragma unroll
            for (int c = 0; c < 4; c++)
                L[r][c] = (c <= r) ? chols[k * 16 + r * 4 + c] : 0.0f;
        float S[4][4];
#pragma unroll
        for (int r = 0; r < 4; r++)
#pragma unroll
            for (int c = 0; c < 4; c++) {
                float s = (r == c) ? 1.0f : 0.0f;
#pragma unroll
                for (int m = 0; m < 4; m++) s = fmaf(L[r][m], L[c][m], s);
                S[r][c] = s;
                sig[k][r * 4 + c] = s;
            }
        // Cholesky S = M M^T (lower), fully unrolled
        float M[4][4];
#pragma unroll
        for (int r = 0; r < 4; r++) {
#pragma unroll
            for (int c = 0; c < 4; c++) {
                if (c > r) { M[r][c] = 0.0f; continue; }
                float s = S[r][c];
#pragma unroll
                for (int m = 0; m < 4; m++)
                    if (m < c) s = fmaf(-M[r][m], M[c][m], s);
                if (r == c) M[r][r] = sqrtf(s);
                else        M[r][c] = s / M[c][c];
            }
        }
        // A = M^{-1} (lower triangular)
        float A[4][4];
#pragma unroll
        for (int r = 0; r < 4; r++) {
#pragma unroll
            for (int c = 0; c < 4; c++) A[r][c] = 0.0f;
            A[r][r] = 1.0f / M[r][r];
#pragma unroll
            for (int c = 0; c < 4; c++) {
                if (c >= r) continue;
                float s = 0.0f;
#pragma unroll
                for (int m = 0; m < 4; m++)
                    if (m >= c && m < r) s = fmaf(M[r][m], A[m][c], s);
                A[r][c] = -s * A[r][r];
            }
        }
        float logdet = 2.0f * logf(M[0][0] * M[1][1] * M[2][2] * M[3][3]);
        float c2 = -0.5f * (4.0f * LN2PI + logdet) * LOG2E;
        int idx = 0;
#pragma unroll
        for (int r = 0; r < 4; r++)
#pragma unroll
            for (int c = 0; c < 4; c++)
                if (c <= r) g_pre.A[k][idx++] = A[r][c] * SCL;
#pragma unroll
        for (int r = 0; r < 4; r++) {
            float b = 0.0f;
#pragma unroll
            for (int c = 0; c < 4; c++)
                if (c <= r) b = fmaf(A[r][c], means[k * 4 + c], b);
            g_pre.B[k][r] = -b * SCL;
        }
        g_pre.C2[k] = c2;
    }
    __syncthreads();

    // ---- W = softmax(w_i * w_j) over all 64 entries (2 warps) ----
    const int i = t >> 3, j = t & 7;
    float wij = weights[i] * weights[j];
    float m = wij;
#pragma unroll
    for (int o = 16; o > 0; o >>= 1) m = fmaxf(m, __shfl_xor_sync(full, m, o));
    if (lane == 0) red0[warp] = m;
    __syncthreads();
    m = fmaxf(red0[0], red0[1]);
    float e = __expf(wij - m);
    float s = e;
#pragma unroll
    for (int o = 16; o > 0; o >>= 1) s += __shfl_xor_sync(full, s, o);
    if (lane == 0) red1[warp] = s;
    __syncthreads();
    s = red1[0] + red1[1];
    float Wij = e / s;
    Wsh[i][j] = Wij;
    __syncthreads();
    if (t == 0) {
        int idx = 0;
#pragma unroll
        for (int a = 0; a < KC; a++) {
            g_pre.WP[idx++] = Wsh[a][a];
#pragma unroll
            for (int b = a + 1; b < KC; b++) g_pre.WP[idx++] = 2.0f * Wsh[a][b];
        }
    }

    // ---- z = sum_ij W_ij * N(mu_i; mu_j, S_i + S_j), one pair per thread ----
    {
        float Ss[4][4];
#pragma unroll
        for (int r = 0; r < 4; r++)
#pragma unroll
            for (int c = 0; c < 4; c++)
                Ss[r][c] = sig[i][r * 4 + c] + sig[j][r * 4 + c];
        float M[4][4];
#pragma unroll
        for (int r = 0; r < 4; r++) {
#pragma unroll
            for (int c = 0; c < 4; c++) {
                if (c > r) { M[r][c] = 0.0f; continue; }
                float s2 = Ss[r][c];
#pragma unroll
                for (int mm = 0; mm < 4; mm++)
                    if (mm < c) s2 = fmaf(-M[r][mm], M[c][mm], s2);
                if (r == c) M[r][r] = sqrtf(s2);
                else        M[r][c] = s2 / M[c][c];
            }
        }
        float ld = 2.0f * logf(M[0][0] * M[1][1] * M[2][2] * M[3][3]);
        float y[4];
#pragma unroll
        for (int r = 0; r < 4; r++) {
            float s2 = means[i * 4 + r] - means[j * 4 + r];
#pragma unroll
            for (int mm = 0; mm < 4; mm++)
                if (mm < r) s2 = fmaf(-M[r][mm], y[mm], s2);
            y[r] = s2 / M[r][r];
        }
        float md = y[0] * y[0] + y[1] * y[1] + y[2] * y[2] + y[3] * y[3];
        float nt = __expf(-0.5f * md - 0.5f * (4.0f * LN2PI + ld));
        float zc = Wij * nt;
#pragma unroll
        for (int o = 16; o > 0; o >>= 1) zc += __shfl_xor_sync(full, zc, o);
        if (lane == 0) red2[warp] = zc;
    }
    __syncthreads();
    if (t == 0) g_pre.logz = logf(red2[0] + red2[1]);
    (void)zpart;
}

// ---------------- main: per-point densities + W-quadratic + reduction ----------------
__global__ void __launch_bounds__(NTHREADS) gmm_main(const float4* __restrict__ X, int N) {
    // pull all constants into registers once
    float A[KC][10], B[KC][4], C2[KC], WP[36];
#pragma unroll
    for (int k = 0; k < KC; k++) {
#pragma unroll
        for (int t = 0; t < 10; t++) A[k][t] = g_pre.A[k][t];
#pragma unroll
        for (int t = 0; t < 4; t++)  B[k][t] = g_pre.B[k][t];
        C2[k] = g_pre.C2[k];
    }
#pragma unroll
    for (int t = 0; t < 36; t++) WP[t] = g_pre.WP[t];

    double acc = 0.0;
    const int stride = gridDim.x * blockDim.x;
    for (int i = blockIdx.x * blockDim.x + threadIdx.x; i < N; i += stride) {
        float4 x = X[i];
        float d[KC];
#pragma unroll
        for (int k = 0; k < KC; k++) {
            float y0 = fmaf(A[k][0], x.x, B[k][0]);
            float y1 = fmaf(A[k][1], x.x, fmaf(A[k][2], x.y, B[k][1]));
            float y2 = fmaf(A[k][3], x.x, fmaf(A[k][4], x.y, fmaf(A[k][5], x.z, B[k][2])));
            float y3 = fmaf(A[k][6], x.x, fmaf(A[k][7], x.y, fmaf(A[k][8], x.z, fmaf(A[k][9], x.w, B[k][3]))));
            float tq = C2[k];
            tq = fmaf(-y0, y0, tq);
            tq = fmaf(-y1, y1, tq);
            tq = fmaf(-y2, y2, tq);
            tq = fmaf(-y3, y3, tq);
            float ev;
            asm("ex2.approx.f32 %0, %1;" : "=f"(ev) : "f"(tq));
            d[k] = ev;
        }
        // num = d^T W d, symmetric packing (36 + 8 FMA)
        float num = 0.f;
        int idx = 0;
#pragma unroll
        for (int a = 0; a < KC; a++) {
            float h = WP[idx++] * d[a];
#pragma unroll
            for (int b = a + 1; b < KC; b++) h = fmaf(WP[idx++], d[b], h);
            num = fmaf(d[a], h, num);
        }
        acc += (double)num;
    }

    // block reduction (double)
    unsigned full = 0xffffffffu;
#pragma unroll
    for (int o = 16; o > 0; o >>= 1) acc += __shfl_down_sync(full, acc, o);
    __shared__ double sred[NTHREADS / 32];
    int w = threadIdx.x >> 5, l = threadIdx.x & 31;
    if (l == 0) sred[w] = acc;
    __syncthreads();
    if (w == 0) {
        double v = (l < NTHREADS / 32) ? sred[l] : 0.0;
#pragma unroll
        for (int o = 4; o > 0; o >>= 1) v += __shfl_down_sync(full, v, o);
        if (l == 0) g_part[blockIdx.x] = v;
    }
}

// ---------------- finalize: warp-parallel ----------------
__global__ void gmm_final(float* __restrict__ out, int N) {
    const int l = threadIdx.x;
    double s = 0;
    for (int b = l; b < GRID; b += 32) s += g_part[b];
#pragma unroll
    for (int o = 16; o > 0; o >>= 1) s += __shfl_down_sync(0xffffffffu, s, o);
    if (l == 0)
        out[0] = (float)(-(log(s) - (double)g_pre.logz) / (double)N);
}

extern "C" void kernel_launch(void* const* d_in, const int* in_sizes, int n_in,
                              void* d_out, int out_size) {
    const float* X       = (const float*)d_in[0];
    const float* means   = (const float*)d_in[1];
    const float* chols   = (const float*)d_in[2];
    const float* weights = (const float*)d_in[3];
    const int N = in_sizes[0] / 4;
    float* out = (float*)d_out;

    gmm_setup<<<1, 64>>>(means, chols, weights);
    gmm_main<<<GRID, NTHREADS>>>((const float4*)X, N);
    gmm_final<<<1, 32>>>(out, N);
}

// round 3
// speedup vs baseline: 2.4928x; 1.1767x over previous
#include <cuda_runtime.h>
#include <math.h>

#define KC 8
#define GRID 296
#define NTHREADS 128

typedef unsigned long long ull;

__device__ double g_part[GRID];
__device__ unsigned int g_ctr;   // zero-init; finalizer resets to 0 each run

// ---- packed f32x2 helpers ----
__device__ __forceinline__ ull f2fma(ull a, ull b, ull c) {
    ull r; asm("fma.rn.f32x2 %0, %1, %2, %3;" : "=l"(r) : "l"(a), "l"(b), "l"(c)); return r;
}
__device__ __forceinline__ ull f2mul(ull a, ull b) {
    ull r; asm("mul.rn.f32x2 %0, %1, %2;" : "=l"(r) : "l"(a), "l"(b)); return r;
}
__device__ __forceinline__ ull pk2(float lo, float hi) {
    ull r; asm("mov.b64 %0, {%1, %2};" : "=l"(r) : "f"(lo), "f"(hi)); return r;
}
__device__ __forceinline__ void upk2(ull v, float& lo, float& hi) {
    asm("mov.b64 {%0, %1}, %2;" : "=f"(lo), "=f"(hi) : "l"(v));
}
__device__ __forceinline__ float ex2f(float x) {
    float r; asm("ex2.approx.f32 %0, %1;" : "=f"(r) : "f"(x)); return r;
}

// =======================================================================
// ONE fused kernel: per-block redundant setup -> main loop -> last-block
// finalize via threadfence + atomic counter.
// =======================================================================
__global__ void __launch_bounds__(NTHREADS) gmm_all(
    const float4* __restrict__ X,
    const float*  __restrict__ means,
    const float*  __restrict__ chols,
    const float*  __restrict__ weights,
    float* __restrict__ out, int N)
{
    __shared__ float sA[KC][10];     // scaled tri rows of M^{-1}
    __shared__ float sB[KC][4];
    __shared__ float sC2[KC];
    __shared__ float sW[KC][KC];     // full symmetric softmax W
    __shared__ float sSig[KC][16];
    __shared__ float red0[2], red1[2], red2[2];
    __shared__ float slogz;
    __shared__ double sred[NTHREADS / 32];
    __shared__ int s_last;

    const int t = threadIdx.x;
    const int lane = t & 31, warp = t >> 5;
    const unsigned full = 0xffffffffu;
    const float LOG2E = 1.4426950408889634f;
    const float LN2PI = 1.8378770664093454f;
    const float SCL   = 0.8493218002880191f;   // sqrt(0.5*log2(e))

    // ---------------- setup phase 1: per-cluster constants (threads 0..7) ----
    if (t < KC) {
        const int k = t;
        float L[4][4];
#pragma unroll
        for (int r = 0; r < 4; r++)
#pragma unroll
            for (int c = 0; c < 4; c++)
                L[r][c] = (c <= r) ? chols[k * 16 + r * 4 + c] : 0.0f;
        float S[4][4];
#pragma unroll
        for (int r = 0; r < 4; r++)
#pragma unroll
            for (int c = 0; c < 4; c++) {
                float s = (r == c) ? 1.0f : 0.0f;
#pragma unroll
                for (int m = 0; m < 4; m++) s = fmaf(L[r][m], L[c][m], s);
                S[r][c] = s;
                sSig[k][r * 4 + c] = s;
            }
        float M[4][4];
#pragma unroll
        for (int r = 0; r < 4; r++) {
#pragma unroll
            for (int c = 0; c < 4; c++) {
                if (c > r) { M[r][c] = 0.0f; continue; }
                float s = S[r][c];
#pragma unroll
                for (int m = 0; m < 4; m++)
                    if (m < c) s = fmaf(-M[r][m], M[c][m], s);
                if (r == c) M[r][r] = sqrtf(s);
                else        M[r][c] = s / M[c][c];
            }
        }
        float A[4][4];
#pragma unroll
        for (int r = 0; r < 4; r++) {
#pragma unroll
            for (int c = 0; c < 4; c++) A[r][c] = 0.0f;
            A[r][r] = 1.0f / M[r][r];
#pragma unroll
            for (int c = 0; c < 4; c++) {
                if (c >= r) continue;
                float s = 0.0f;
#pragma unroll
                for (int m = 0; m < 4; m++)
                    if (m >= c && m < r) s = fmaf(M[r][m], A[m][c], s);
                A[r][c] = -s * A[r][r];
            }
        }
        float logdet = 2.0f * logf(M[0][0] * M[1][1] * M[2][2] * M[3][3]);
        sC2[k] = -0.5f * (4.0f * LN2PI + logdet) * LOG2E;
        int idx = 0;
#pragma unroll
        for (int r = 0; r < 4; r++)
#pragma unroll
            for (int c = 0; c < 4; c++)
                if (c <= r) sA[k][idx++] = A[r][c] * SCL;
#pragma unroll
        for (int r = 0; r < 4; r++) {
            float b = 0.0f;
#pragma unroll
            for (int c = 0; c < 4; c++)
                if (c <= r) b = fmaf(A[r][c], means[k * 4 + c], b);
            sB[k][r] = -b * SCL;
        }
    }
    __syncthreads();

    // ---------------- setup phase 2: softmax W + z (threads 0..63) ----------
    const int i8 = t >> 3, j8 = t & 7;
    float wij = 0.0f, m = -1e30f;
    if (t < 64) {
        wij = weights[i8] * weights[j8];
        m = wij;
#pragma unroll
        for (int o = 16; o > 0; o >>= 1) m = fmaxf(m, __shfl_xor_sync(full, m, o));
        if (lane == 0) red0[warp] = m;
    }
    __syncthreads();
    float e = 0.0f;
    if (t < 64) {
        m = fmaxf(red0[0], red0[1]);
        e = __expf(wij - m);
        float s = e;
#pragma unroll
        for (int o = 16; o > 0; o >>= 1) s += __shfl_xor_sync(full, s, o);
        if (lane == 0) red1[warp] = s;
    }
    __syncthreads();
    if (t < 64) {
        float s = red1[0] + red1[1];
        float Wij = e / s;
        sW[i8][j8] = Wij;
        // z contribution for pair (i8, j8)
        float Ss[4][4];
#pragma unroll
        for (int r = 0; r < 4; r++)
#pragma unroll
            for (int c = 0; c < 4; c++)
                Ss[r][c] = sSig[i8][r * 4 + c] + sSig[j8][r * 4 + c];
        float M[4][4];
#pragma unroll
        for (int r = 0; r < 4; r++) {
#pragma unroll
            for (int c = 0; c < 4; c++) {
                if (c > r) { M[r][c] = 0.0f; continue; }
                float s2 = Ss[r][c];
#pragma unroll
                for (int mm = 0; mm < 4; mm++)
                    if (mm < c) s2 = fmaf(-M[r][mm], M[c][mm], s2);
                if (r == c) M[r][r] = sqrtf(s2);
                else        M[r][c] = s2 / M[c][c];
            }
        }
        float ld = 2.0f * logf(M[0][0] * M[1][1] * M[2][2] * M[3][3]);
        float y[4];
#pragma unroll
        for (int r = 0; r < 4; r++) {
            float s2 = means[i8 * 4 + r] - means[j8 * 4 + r];
#pragma unroll
            for (int mm = 0; mm < 4; mm++)
                if (mm < r) s2 = fmaf(-M[r][mm], y[mm], s2);
            y[r] = s2 / M[r][r];
        }
        float md = y[0] * y[0] + y[1] * y[1] + y[2] * y[2] + y[3] * y[3];
        float zc = Wij * __expf(-0.5f * md - 0.5f * (4.0f * LN2PI + ld));
#pragma unroll
        for (int o = 16; o > 0; o >>= 1) zc += __shfl_xor_sync(full, zc, o);
        if (lane == 0) red2[warp] = zc;
    }
    __syncthreads();
    if (t == 0) slogz = logf(red2[0] + red2[1]);
    __syncthreads();

    // ---------------- load + pack constants into registers -------------------
    // cluster pairs p: clusters (2p, 2p+1)
    ull PA[4][10], PB[4][4], PW[4][8];
    float C2r[KC];
#pragma unroll
    for (int p = 0; p < 4; p++) {
#pragma unroll
        for (int q = 0; q < 10; q++) PA[p][q] = pk2(sA[2 * p][q], sA[2 * p + 1][q]);
#pragma unroll
        for (int q = 0; q < 4; q++)  PB[p][q] = pk2(sB[2 * p][q], sB[2 * p + 1][q]);
#pragma unroll
        for (int b = 0; b < 8; b++)  PW[p][b] = pk2(sW[2 * p][b], sW[2 * p + 1][b]);
    }
#pragma unroll
    for (int k = 0; k < KC; k++) C2r[k] = sC2[k];

    // ---------------- main loop ----------------------------------------------
    double acc = 0.0;
    const int stride = gridDim.x * blockDim.x;
    for (int i = blockIdx.x * blockDim.x + t; i < N; i += stride) {
        float4 x = X[i];
        ull Xx = pk2(x.x, x.x), Xy = pk2(x.y, x.y), Xz = pk2(x.z, x.z), Xw = pk2(x.w, x.w);
        float d[KC];
#pragma unroll
        for (int p = 0; p < 4; p++) {
            ull y0 = f2fma(PA[p][0], Xx, PB[p][0]);
            ull y1 = f2fma(PA[p][1], Xx, f2fma(PA[p][2], Xy, PB[p][1]));
            ull y2 = f2fma(PA[p][3], Xx, f2fma(PA[p][4], Xy, f2fma(PA[p][5], Xz, PB[p][2])));
            ull y3 = f2fma(PA[p][6], Xx, f2fma(PA[p][7], Xy, f2fma(PA[p][8], Xz, f2fma(PA[p][9], Xw, PB[p][3]))));
            ull s = f2mul(y0, y0);
            s = f2fma(y1, y1, s);
            s = f2fma(y2, y2, s);
            s = f2fma(y3, y3, s);
            float s0, s1;
            upk2(s, s0, s1);
            d[2 * p]     = ex2f(C2r[2 * p]     - s0);
            d[2 * p + 1] = ex2f(C2r[2 * p + 1] - s1);
        }
        // num = d^T W d, rows packed in pairs
        ull dd[KC];
#pragma unroll
        for (int b = 0; b < KC; b++) dd[b] = pk2(d[b], d[b]);
        float num = 0.0f;
#pragma unroll
        for (int p = 0; p < 4; p++) {
            ull h = f2mul(PW[p][0], dd[0]);
#pragma unroll
            for (int b = 1; b < 8; b++) h = f2fma(PW[p][b], dd[b], h);
            float ha, hb;
            upk2(h, ha, hb);
            num = fmaf(d[2 * p], ha, num);
            num = fmaf(d[2 * p + 1], hb, num);
        }
        acc += (double)num;
    }

    // ---------------- block reduction (double) -------------------------------
#pragma unroll
    for (int o = 16; o > 0; o >>= 1) acc += __shfl_down_sync(full, acc, o);
    if (lane == 0) sred[warp] = acc;
    __syncthreads();
    if (t == 0) {
        double v = 0.0;
#pragma unroll
        for (int w2 = 0; w2 < NTHREADS / 32; w2++) v += sred[w2];
        g_part[blockIdx.x] = v;
        __threadfence();
        unsigned old = atomicAdd(&g_ctr, 1u);
        s_last = (old == gridDim.x - 1) ? 1 : 0;
    }
    __syncthreads();

    // ---------------- last block finalizes -----------------------------------
    if (s_last && warp == 0) {
        double s = 0.0;
        for (int b = lane; b < GRID; b += 32) s += g_part[b];
#pragma unroll
        for (int o = 16; o > 0; o >>= 1) s += __shfl_down_sync(full, s, o);
        if (lane == 0) {
            out[0] = (float)(-(log(s) - (double)slogz) / (double)N);
            g_ctr = 0;   // reset for next graph replay
        }
    }
}

extern "C" void kernel_launch(void* const* d_in, const int* in_sizes, int n_in,
                              void* d_out, int out_size) {
    const float* X       = (const float*)d_in[0];
    const float* means   = (const float*)d_in[1];
    const float* chols   = (const float*)d_in[2];
    const float* weights = (const float*)d_in[3];
    const int N = in_sizes[0] / 4;
    float* out = (float*)d_out;

    gmm_all<<<GRID, NTHREADS>>>((const float4*)X, means, chols, weights, out, N);
}

// round 4
// speedup vs baseline: 2.6769x; 1.0738x over previous
#include <cuda_runtime.h>
#include <math.h>

#define KC 8
#define GRID 296
#define NTHREADS 128

typedef unsigned long long ull;

__device__ double g_part[GRID];
__device__ unsigned int g_ctr;   // zero-init; finalizer resets to 0 each run

// ---- packed f32x2 helpers ----
__device__ __forceinline__ ull f2fma(ull a, ull b, ull c) {
    ull r; asm("fma.rn.f32x2 %0, %1, %2, %3;" : "=l"(r) : "l"(a), "l"(b), "l"(c)); return r;
}
__device__ __forceinline__ ull f2mul(ull a, ull b) {
    ull r; asm("mul.rn.f32x2 %0, %1, %2;" : "=l"(r) : "l"(a), "l"(b)); return r;
}
__device__ __forceinline__ ull pk2(float lo, float hi) {
    ull r; asm("mov.b64 %0, {%1, %2};" : "=l"(r) : "f"(lo), "f"(hi)); return r;
}
__device__ __forceinline__ void upk2(ull v, float& lo, float& hi) {
    asm("mov.b64 {%0, %1}, %2;" : "=f"(lo), "=f"(hi) : "l"(v));
}
__device__ __forceinline__ float ex2f(float x) {
    float r; asm("ex2.approx.f32 %0, %1;" : "=f"(r) : "f"(x)); return r;
}

// per-point density + quadratic, given packed constants
__device__ __forceinline__ float point_num(
    float4 x, const ull PA[4][10], const ull PB[4][4],
    const float C2r[KC], const float WP[36])
{
    ull Xx = pk2(x.x, x.x), Xy = pk2(x.y, x.y), Xz = pk2(x.z, x.z), Xw = pk2(x.w, x.w);
    float d[KC];
#pragma unroll
    for (int p = 0; p < 4; p++) {
        ull y0 = f2fma(PA[p][0], Xx, PB[p][0]);
        ull y1 = f2fma(PA[p][1], Xx, f2fma(PA[p][2], Xy, PB[p][1]));
        ull y2 = f2fma(PA[p][3], Xx, f2fma(PA[p][4], Xy, f2fma(PA[p][5], Xz, PB[p][2])));
        ull y3 = f2fma(PA[p][6], Xx, f2fma(PA[p][7], Xy, f2fma(PA[p][8], Xz, f2fma(PA[p][9], Xw, PB[p][3]))));
        ull s = f2mul(y0, y0);
        s = f2fma(y1, y1, s);
        s = f2fma(y2, y2, s);
        s = f2fma(y3, y3, s);
        float s0, s1;
        upk2(s, s0, s1);
        d[2 * p]     = ex2f(C2r[2 * p]     - s0);
        d[2 * p + 1] = ex2f(C2r[2 * p + 1] - s1);
    }
    // num = d^T W d, symmetric packing (36 + 8 scalar FMA, 8 independent chains)
    float num = 0.0f;
    int idx = 0;
#pragma unroll
    for (int a = 0; a < KC; a++) {
        float h = WP[idx++] * d[a];
#pragma unroll
        for (int b = a + 1; b < KC; b++) h = fmaf(WP[idx++], d[b], h);
        num = fmaf(d[a], h, num);
    }
    return num;
}

// =======================================================================
// ONE fused kernel: per-block redundant setup -> main loop (2-pt unroll)
// -> last-block finalize via threadfence + atomic counter.
// =======================================================================
__global__ void __launch_bounds__(NTHREADS) gmm_all(
    const float4* __restrict__ X,
    const float*  __restrict__ means,
    const float*  __restrict__ chols,
    const float*  __restrict__ weights,
    float* __restrict__ out, int N)
{
    __shared__ float sA[KC][10];
    __shared__ float sB[KC][4];
    __shared__ float sC2[KC];
    __shared__ float sW[KC][KC];
    __shared__ float sSig[KC][16];
    __shared__ float red0[2], red1[2], red2[2];
    __shared__ float slogz;
    __shared__ double sred[NTHREADS / 32];
    __shared__ int s_last;

    const int t = threadIdx.x;
    const int lane = t & 31, warp = t >> 5;
    const unsigned full = 0xffffffffu;
    const float LOG2E = 1.4426950408889634f;
    const float LN2PI = 1.8378770664093454f;
    const float SCL   = 0.8493218002880191f;   // sqrt(0.5*log2(e))

    // ---------------- setup phase 1: per-cluster constants (threads 0..7) ----
    if (t < KC) {
        const int k = t;
        float L[4][4];
#pragma unroll
        for (int r = 0; r < 4; r++)
#pragma unroll
            for (int c = 0; c < 4; c++)
                L[r][c] = (c <= r) ? chols[k * 16 + r * 4 + c] : 0.0f;
        float S[4][4];
#pragma unroll
        for (int r = 0; r < 4; r++)
#pragma unroll
            for (int c = 0; c < 4; c++) {
                float s = (r == c) ? 1.0f : 0.0f;
#pragma unroll
                for (int m = 0; m < 4; m++) s = fmaf(L[r][m], L[c][m], s);
                S[r][c] = s;
                sSig[k][r * 4 + c] = s;
            }
        float M[4][4];
#pragma unroll
        for (int r = 0; r < 4; r++) {
#pragma unroll
            for (int c = 0; c < 4; c++) {
                if (c > r) { M[r][c] = 0.0f; continue; }
                float s = S[r][c];
#pragma unroll
                for (int m = 0; m < 4; m++)
                    if (m < c) s = fmaf(-M[r][m], M[c][m], s);
                if (r == c) M[r][r] = sqrtf(s);
                else        M[r][c] = s / M[c][c];
            }
        }
        float A[4][4];
#pragma unroll
        for (int r = 0; r < 4; r++) {
#pragma unroll
            for (int c = 0; c < 4; c++) A[r][c] = 0.0f;
            A[r][r] = 1.0f / M[r][r];
#pragma unroll
            for (int c = 0; c < 4; c++) {
                if (c >= r) continue;
                float s = 0.0f;
#pragma unroll
                for (int m = 0; m < 4; m++)
                    if (m >= c && m < r) s = fmaf(M[r][m], A[m][c], s);
                A[r][c] = -s * A[r][r];
            }
        }
        float logdet = 2.0f * logf(M[0][0] * M[1][1] * M[2][2] * M[3][3]);
        sC2[k] = -0.5f * (4.0f * LN2PI + logdet) * LOG2E;
        int idx = 0;
#pragma unroll
        for (int r = 0; r < 4; r++)
#pragma unroll
            for (int c = 0; c < 4; c++)
                if (c <= r) sA[k][idx++] = A[r][c] * SCL;
#pragma unroll
        for (int r = 0; r < 4; r++) {
            float b = 0.0f;
#pragma unroll
            for (int c = 0; c < 4; c++)
                if (c <= r) b = fmaf(A[r][c], means[k * 4 + c], b);
            sB[k][r] = -b * SCL;
        }
    }
    __syncthreads();

    // ---------------- setup phase 2: softmax W + z (threads 0..63) ----------
    const int i8 = t >> 3, j8 = t & 7;
    float wij = 0.0f, m = -1e30f;
    if (t < 64) {
        wij = weights[i8] * weights[j8];
        m = wij;
#pragma unroll
        for (int o = 16; o > 0; o >>= 1) m = fmaxf(m, __shfl_xor_sync(full, m, o));
        if (lane == 0) red0[warp] = m;
    }
    __syncthreads();
    float e = 0.0f;
    if (t < 64) {
        m = fmaxf(red0[0], red0[1]);
        e = __expf(wij - m);
        float s = e;
#pragma unroll
        for (int o = 16; o > 0; o >>= 1) s += __shfl_xor_sync(full, s, o);
        if (lane == 0) red1[warp] = s;
    }
    __syncthreads();
    if (t < 64) {
        float s = red1[0] + red1[1];
        float Wij = e / s;
        sW[i8][j8] = Wij;
        float Ss[4][4];
#pragma unroll
        for (int r = 0; r < 4; r++)
#pragma unroll
            for (int c = 0; c < 4; c++)
                Ss[r][c] = sSig[i8][r * 4 + c] + sSig[j8][r * 4 + c];
        float M[4][4];
#pragma unroll
        for (int r = 0; r < 4; r++) {
#pragma unroll
            for (int c = 0; c < 4; c++) {
                if (c > r) { M[r][c] = 0.0f; continue; }
                float s2 = Ss[r][c];
#pragma unroll
                for (int mm = 0; mm < 4; mm++)
                    if (mm < c) s2 = fmaf(-M[r][mm], M[c][mm], s2);
                if (r == c) M[r][r] = sqrtf(s2);
                else        M[r][c] = s2 / M[c][c];
            }
        }
        float ld = 2.0f * logf(M[0][0] * M[1][1] * M[2][2] * M[3][3]);
        float y[4];
#pragma unroll
        for (int r = 0; r < 4; r++) {
            float s2 = means[i8 * 4 + r] - means[j8 * 4 + r];
#pragma unroll
            for (int mm = 0; mm < 4; mm++)
                if (mm < r) s2 = fmaf(-M[r][mm], y[mm], s2);
            y[r] = s2 / M[r][r];
        }
        float md = y[0] * y[0] + y[1] * y[1] + y[2] * y[2] + y[3] * y[3];
        float zc = Wij * __expf(-0.5f * md - 0.5f * (4.0f * LN2PI + ld));
#pragma unroll
        for (int o = 16; o > 0; o >>= 1) zc += __shfl_xor_sync(full, zc, o);
        if (lane == 0) red2[warp] = zc;
    }
    __syncthreads();
    if (t == 0) slogz = logf(red2[0] + red2[1]);
    __syncthreads();

    // ---------------- load + pack constants into registers -------------------
    ull PA[4][10], PB[4][4];
    float C2r[KC], WP[36];
#pragma unroll
    for (int p = 0; p < 4; p++) {
#pragma unroll
        for (int q = 0; q < 10; q++) PA[p][q] = pk2(sA[2 * p][q], sA[2 * p + 1][q]);
#pragma unroll
        for (int q = 0; q < 4; q++)  PB[p][q] = pk2(sB[2 * p][q], sB[2 * p + 1][q]);
    }
#pragma unroll
    for (int k = 0; k < KC; k++) C2r[k] = sC2[k];
    {
        int idx = 0;
#pragma unroll
        for (int a = 0; a < KC; a++) {
            WP[idx++] = sW[a][a];
#pragma unroll
            for (int b = a + 1; b < KC; b++) WP[idx++] = 2.0f * sW[a][b];
        }
    }

    // ---------------- main loop: 2 points per iteration ----------------------
    double acc = 0.0;
    const int stride = gridDim.x * blockDim.x;
    const int step = 2 * stride;
    for (int i = blockIdx.x * blockDim.x + t; i < N; i += step) {
        const int i2 = i + stride;
        const bool v2 = (i2 < N);
        float4 x1 = X[i];
        float4 x2 = v2 ? X[i2] : x1;     // both loads issued before compute (MLP=2)

        float num1 = point_num(x1, PA, PB, C2r, WP);
        float num2 = point_num(x2, PA, PB, C2r, WP);

        acc += (double)(v2 ? (num1 + num2) : num1);
    }

    // ---------------- block reduction (double) -------------------------------
#pragma unroll
    for (int o = 16; o > 0; o >>= 1) acc += __shfl_down_sync(full, acc, o);
    if (lane == 0) sred[warp] = acc;
    __syncthreads();
    if (t == 0) {
        double v = 0.0;
#pragma unroll
        for (int w2 = 0; w2 < NTHREADS / 32; w2++) v += sred[w2];
        g_part[blockIdx.x] = v;
        __threadfence();
        unsigned old = atomicAdd(&g_ctr, 1u);
        s_last = (old == gridDim.x - 1) ? 1 : 0;
    }
    __syncthreads();

    // ---------------- last block finalizes -----------------------------------
    if (s_last && warp == 0) {
        double s = 0.0;
        for (int b = lane; b < GRID; b += 32) s += g_part[b];
#pragma unroll
        for (int o = 16; o > 0; o >>= 1) s += __shfl_down_sync(full, s, o);
        if (lane == 0) {
            out[0] = (float)(-(log(s) - (double)slogz) / (double)N);
            g_ctr = 0;   // reset for next graph replay
        }
    }
}

extern "C" void kernel_launch(void* const* d_in, const int* in_sizes, int n_in,
                              void* d_out, int out_size) {
    const float* X       = (const float*)d_in[0];
    const float* means   = (const float*)d_in[1];
    const float* chols   = (const float*)d_in[2];
    const float* weights = (const float*)d_in[3];
    const int N = in_sizes[0] / 4;
    float* out = (float*)d_out;

    gmm_all<<<GRID, NTHREADS>>>((const float4*)X, means, chols, weights, out, N);
}

// round 5
// speedup vs baseline: 2.8370x; 1.0598x over previous
#include <cuda_runtime.h>
#include <math.h>

#define KC 8
#define GRID 296
#define NTHREADS 128

typedef unsigned long long ull;

__device__ double g_part[GRID];
__device__ unsigned int g_ctr;   // zero-init; finalizer resets to 0 each run

// ---- packed f32x2 helpers ----
__device__ __forceinline__ ull f2fma(ull a, ull b, ull c) {
    ull r; asm("fma.rn.f32x2 %0, %1, %2, %3;" : "=l"(r) : "l"(a), "l"(b), "l"(c)); return r;
}
__device__ __forceinline__ ull f2mul(ull a, ull b) {
    ull r; asm("mul.rn.f32x2 %0, %1, %2;" : "=l"(r) : "l"(a), "l"(b)); return r;
}
__device__ __forceinline__ ull pk2(float lo, float hi) {
    ull r; asm("mov.b64 %0, {%1, %2};" : "=l"(r) : "f"(lo), "f"(hi)); return r;
}
__device__ __forceinline__ void upk2(ull v, float& lo, float& hi) {
    asm("mov.b64 {%0, %1}, %2;" : "=f"(lo), "=f"(hi) : "l"(v));
}
__device__ __forceinline__ float ex2f(float x) {
    float r; asm("ex2.approx.f32 %0, %1;" : "=f"(r) : "f"(x)); return r;
}

// per-point density + quadratic, given packed constants
__device__ __forceinline__ float point_num(
    float4 x, const ull PA[4][10], const ull PB[4][4],
    const float C2r[KC], const float WP[36])
{
    ull Xx = pk2(x.x, x.x), Xy = pk2(x.y, x.y), Xz = pk2(x.z, x.z), Xw = pk2(x.w, x.w);
    float d[KC];
#pragma unroll
    for (int p = 0; p < 4; p++) {
        ull y0 = f2fma(PA[p][0], Xx, PB[p][0]);
        ull y1 = f2fma(PA[p][1], Xx, f2fma(PA[p][2], Xy, PB[p][1]));
        ull y2 = f2fma(PA[p][3], Xx, f2fma(PA[p][4], Xy, f2fma(PA[p][5], Xz, PB[p][2])));
        ull y3 = f2fma(PA[p][6], Xx, f2fma(PA[p][7], Xy, f2fma(PA[p][8], Xz, f2fma(PA[p][9], Xw, PB[p][3]))));
        ull s = f2mul(y0, y0);
        s = f2fma(y1, y1, s);
        s = f2fma(y2, y2, s);
        s = f2fma(y3, y3, s);
        float s0, s1;
        upk2(s, s0, s1);
        d[2 * p]     = ex2f(C2r[2 * p]     - s0);
        d[2 * p + 1] = ex2f(C2r[2 * p + 1] - s1);
    }
    // num = d^T W d, symmetric packing (36 + 8 scalar FMA, 8 independent chains)
    float num = 0.0f;
    int idx = 0;
#pragma unroll
    for (int a = 0; a < KC; a++) {
        float h = WP[idx++] * d[a];
#pragma unroll
        for (int b = a + 1; b < KC; b++) h = fmaf(WP[idx++], d[b], h);
        num = fmaf(d[a], h, num);
    }
    return num;
}

// =======================================================================
// ONE fused kernel: per-block redundant setup -> main loop (4-pt unroll,
// adjacent points, no per-point guards) -> last-block finalize.
// =======================================================================
__global__ void __launch_bounds__(NTHREADS) gmm_all(
    const float4* __restrict__ X,
    const float*  __restrict__ means,
    const float*  __restrict__ chols,
    const float*  __restrict__ weights,
    float* __restrict__ out, int N)
{
    __shared__ float sA[KC][10];
    __shared__ float sB[KC][4];
    __shared__ float sC2[KC];
    __shared__ float sW[KC][KC];
    __shared__ float sSig[KC][16];
    __shared__ float red0[2], red1[2], red2[2];
    __shared__ float slogz;
    __shared__ double sred[NTHREADS / 32];
    __shared__ int s_last;

    const int t = threadIdx.x;
    const int lane = t & 31, warp = t >> 5;
    const unsigned full = 0xffffffffu;
    const float LOG2E = 1.4426950408889634f;
    const float LN2PI = 1.8378770664093454f;
    const float SCL   = 0.8493218002880191f;   // sqrt(0.5*log2(e))

    // ---------------- setup phase 1: per-cluster constants (threads 0..7) ----
    if (t < KC) {
        const int k = t;
        float L[4][4];
#pragma unroll
        for (int r = 0; r < 4; r++)
#pragma unroll
            for (int c = 0; c < 4; c++)
                L[r][c] = (c <= r) ? chols[k * 16 + r * 4 + c] : 0.0f;
        float S[4][4];
#pragma unroll
        for (int r = 0; r < 4; r++)
#pragma unroll
            for (int c = 0; c < 4; c++) {
                float s = (r == c) ? 1.0f : 0.0f;
#pragma unroll
                for (int m = 0; m < 4; m++) s = fmaf(L[r][m], L[c][m], s);
                S[r][c] = s;
                sSig[k][r * 4 + c] = s;
            }
        float M[4][4];
#pragma unroll
        for (int r = 0; r < 4; r++) {
#pragma unroll
            for (int c = 0; c < 4; c++) {
                if (c > r) { M[r][c] = 0.0f; continue; }
                float s = S[r][c];
#pragma unroll
                for (int m = 0; m < 4; m++)
                    if (m < c) s = fmaf(-M[r][m], M[c][m], s);
                if (r == c) M[r][r] = sqrtf(s);
                else        M[r][c] = s / M[c][c];
            }
        }
        float A[4][4];
#pragma unroll
        for (int r = 0; r < 4; r++) {
#pragma unroll
            for (int c = 0; c < 4; c++) A[r][c] = 0.0f;
            A[r][r] = 1.0f / M[r][r];
#pragma unroll
            for (int c = 0; c < 4; c++) {
                if (c >= r) continue;
                float s = 0.0f;
#pragma unroll
                for (int m = 0; m < 4; m++)
                    if (m >= c && m < r) s = fmaf(M[r][m], A[m][c], s);
                A[r][c] = -s * A[r][r];
            }
        }
        float logdet = 2.0f * logf(M[0][0] * M[1][1] * M[2][2] * M[3][3]);
        sC2[k] = -0.5f * (4.0f * LN2PI + logdet) * LOG2E;
        int idx = 0;
#pragma unroll
        for (int r = 0; r < 4; r++)
#pragma unroll
            for (int c = 0; c < 4; c++)
                if (c <= r) sA[k][idx++] = A[r][c] * SCL;
#pragma unroll
        for (int r = 0; r < 4; r++) {
            float b = 0.0f;
#pragma unroll
            for (int c = 0; c < 4; c++)
                if (c <= r) b = fmaf(A[r][c], means[k * 4 + c], b);
            sB[k][r] = -b * SCL;
        }
    }
    __syncthreads();

    // ---------------- setup phase 2: softmax W + z (threads 0..63) ----------
    const int i8 = t >> 3, j8 = t & 7;
    float wij = 0.0f, m = -1e30f;
    if (t < 64) {
        wij = weights[i8] * weights[j8];
        m = wij;
#pragma unroll
        for (int o = 16; o > 0; o >>= 1) m = fmaxf(m, __shfl_xor_sync(full, m, o));
        if (lane == 0) red0[warp] = m;
    }
    __syncthreads();
    float e = 0.0f;
    if (t < 64) {
        m = fmaxf(red0[0], red0[1]);
        e = __expf(wij - m);
        float s = e;
#pragma unroll
        for (int o = 16; o > 0; o >>= 1) s += __shfl_xor_sync(full, s, o);
        if (lane == 0) red1[warp] = s;
    }
    __syncthreads();
    if (t < 64) {
        float s = red1[0] + red1[1];
        float Wij = e / s;
        sW[i8][j8] = Wij;
        float Ss[4][4];
#pragma unroll
        for (int r = 0; r < 4; r++)
#pragma unroll
            for (int c = 0; c < 4; c++)
                Ss[r][c] = sSig[i8][r * 4 + c] + sSig[j8][r * 4 + c];
        float M[4][4];
#pragma unroll
        for (int r = 0; r < 4; r++) {
#pragma unroll
            for (int c = 0; c < 4; c++) {
                if (c > r) { M[r][c] = 0.0f; continue; }
                float s2 = Ss[r][c];
#pragma unroll
                for (int mm = 0; mm < 4; mm++)
                    if (mm < c) s2 = fmaf(-M[r][mm], M[c][mm], s2);
                if (r == c) M[r][r] = sqrtf(s2);
                else        M[r][c] = s2 / M[c][c];
            }
        }
        float ld = 2.0f * logf(M[0][0] * M[1][1] * M[2][2] * M[3][3]);
        float y[4];
#pragma unroll
        for (int r = 0; r < 4; r++) {
            float s2 = means[i8 * 4 + r] - means[j8 * 4 + r];
#pragma unroll
            for (int mm = 0; mm < 4; mm++)
                if (mm < r) s2 = fmaf(-M[r][mm], y[mm], s2);
            y[r] = s2 / M[r][r];
        }
        float md = y[0] * y[0] + y[1] * y[1] + y[2] * y[2] + y[3] * y[3];
        float zc = Wij * __expf(-0.5f * md - 0.5f * (4.0f * LN2PI + ld));
#pragma unroll
        for (int o = 16; o > 0; o >>= 1) zc += __shfl_xor_sync(full, zc, o);
        if (lane == 0) red2[warp] = zc;
    }
    __syncthreads();
    if (t == 0) slogz = logf(red2[0] + red2[1]);
    __syncthreads();

    // ---------------- load + pack constants into registers -------------------
    ull PA[4][10], PB[4][4];
    float C2r[KC], WP[36];
#pragma unroll
    for (int p = 0; p < 4; p++) {
#pragma unroll
        for (int q = 0; q < 10; q++) PA[p][q] = pk2(sA[2 * p][q], sA[2 * p + 1][q]);
#pragma unroll
        for (int q = 0; q < 4; q++)  PB[p][q] = pk2(sB[2 * p][q], sB[2 * p + 1][q]);
    }
#pragma unroll
    for (int k = 0; k < KC; k++) C2r[k] = sC2[k];
    {
        int idx = 0;
#pragma unroll
        for (int a = 0; a < KC; a++) {
            WP[idx++] = sW[a][a];
#pragma unroll
            for (int b = a + 1; b < KC; b++) WP[idx++] = 2.0f * sW[a][b];
        }
    }

    // ---------------- main loop: 4 adjacent points per iteration -------------
    double acc = 0.0;
    const int gid = blockIdx.x * blockDim.x + t;
    const int nthr = gridDim.x * blockDim.x;
    const int step = 4 * nthr;
    int i = 4 * gid;
    for (; i + 3 < N; i += step) {
        float4 x0 = X[i];
        float4 x1 = X[i + 1];
        float4 x2 = X[i + 2];
        float4 x3 = X[i + 3];
        float n0 = point_num(x0, PA, PB, C2r, WP);
        float n1 = point_num(x1, PA, PB, C2r, WP);
        float n2 = point_num(x2, PA, PB, C2r, WP);
        float n3 = point_num(x3, PA, PB, C2r, WP);
        acc += (double)((n0 + n1) + (n2 + n3));
    }
    // tail: at most the one straddling group
    for (; i < N; i++)
        acc += (double)point_num(X[i], PA, PB, C2r, WP);

    // ---------------- block reduction (double) -------------------------------
#pragma unroll
    for (int o = 16; o > 0; o >>= 1) acc += __shfl_down_sync(full, acc, o);
    if (lane == 0) sred[warp] = acc;
    __syncthreads();
    if (t == 0) {
        double v = 0.0;
#pragma unroll
        for (int w2 = 0; w2 < NTHREADS / 32; w2++) v += sred[w2];
        g_part[blockIdx.x] = v;
        __threadfence();
        unsigned old = atomicAdd(&g_ctr, 1u);
        s_last = (old == gridDim.x - 1) ? 1 : 0;
    }
    __syncthreads();

    // ---------------- last block finalizes -----------------------------------
    if (s_last && warp == 0) {
        double s = 0.0;
        for (int b = lane; b < GRID; b += 32) s += g_part[b];
#pragma unroll
        for (int o = 16; o > 0; o >>= 1) s += __shfl_down_sync(full, s, o);
        if (lane == 0) {
            out[0] = (float)(-(log(s) - (double)slogz) / (double)N);
            g_ctr = 0;   // reset for next graph replay
        }
    }
}

extern "C" void kernel_launch(void* const* d_in, const int* in_sizes, int n_in,
                              void* d_out, int out_size) {
    const float* X       = (const float*)d_in[0];
    const float* means   = (const float*)d_in[1];
    const float* chols   = (const float*)d_in[2];
    const float* weights = (const float*)d_in[3];
    const int N = in_sizes[0] / 4;
    float* out = (float*)d_out;

    gmm_all<<<GRID, NTHREADS>>>((const float4*)X, means, chols, weights, out, N);
}